// round 13
// baseline (speedup 1.0000x reference)
#include <cuda_runtime.h>
#include <cuda_bf16.h>
#include <math.h>
#include <stdint.h>

#define H 768
#define Bb 4
#define Tt 2048
#define BT (Bb*Tt)            // 8192
#define STAGE_BYTES 65536u    // 4 operand tiles * 16KB (128 rows x 128B)
#define SMEM_BYTES (3*65536)  // 3 stages

// ---------------- device scratch (no allocations allowed) --------------------
__device__ __nv_bfloat16 g_xnh[BT*H], g_xnl[BT*H];
__device__ __nv_bfloat16 g_Qh[BT*H],  g_Ql[BT*H];
__device__ __nv_bfloat16 g_Kh[BT*H],  g_Kl[BT*H];
__device__ __nv_bfloat16 g_Vth[BT*H], g_Vtl[BT*H];   // V^T: [b][d][t]
__device__ float         g_U[BT*H];
__device__ __nv_bfloat16 g_Sh[(size_t)Bb*Tt*Tt], g_Sl[(size_t)Bb*Tt*Tt];
__device__ __nv_bfloat16 g_Mh[BT*H],  g_Ml[BT*H];
__device__ __nv_bfloat16 g_Wh[5*H*H], g_Wl[5*H*H];

// ---------------- PTX helpers ------------------------------------------------
__device__ __forceinline__ uint32_t s2u(const void* p) {
    uint32_t a;
    asm("{ .reg .u64 t; cvta.to.shared.u64 t, %1; cvt.u32.u64 %0, t; }" : "=r"(a) : "l"(p));
    return a;
}
__device__ __forceinline__ void cp16(uint32_t d, const void* s) {
    asm volatile("cp.async.cg.shared.global [%0], [%1], 16;" :: "r"(d), "l"(s));
}
__device__ __forceinline__ void ldmx4(uint32_t* r, uint32_t a) {
    asm volatile("ldmatrix.sync.aligned.m8n8.x4.shared.b16 {%0,%1,%2,%3}, [%4];"
        : "=r"(r[0]), "=r"(r[1]), "=r"(r[2]), "=r"(r[3]) : "r"(a));
}
__device__ __forceinline__ void mma16816(float* c, const uint32_t* a,
                                         uint32_t b0, uint32_t b1) {
    asm volatile("mma.sync.aligned.m16n8k16.row.col.f32.bf16.bf16.f32 "
        "{%0,%1,%2,%3}, {%4,%5,%6,%7}, {%8,%9}, {%0,%1,%2,%3};"
        : "+f"(c[0]), "+f"(c[1]), "+f"(c[2]), "+f"(c[3])
        : "r"(a[0]), "r"(a[1]), "r"(a[2]), "r"(a[3]), "r"(b0), "r"(b1));
}

// ---------------- LayerNorm (fp32 math, bf16 hi/lo output) -------------------
__global__ void ln_kernel(const float* __restrict__ x, const float* __restrict__ gamma,
                          const float* __restrict__ beta,
                          __nv_bfloat16* __restrict__ oh, __nv_bfloat16* __restrict__ ol) {
    int row = blockIdx.x;
    const float* xr = x + (size_t)row * H;
    int t = threadIdx.x;
    float v0 = xr[t], v1 = xr[t + 256], v2 = xr[t + 512];
    float s = v0 + v1 + v2;
    float q = v0 * v0 + v1 * v1 + v2 * v2;
    __shared__ float sm[16];
#pragma unroll
    for (int o = 16; o > 0; o >>= 1) {
        s += __shfl_xor_sync(0xffffffffu, s, o);
        q += __shfl_xor_sync(0xffffffffu, q, o);
    }
    if ((t & 31) == 0) { sm[t >> 5] = s; sm[8 + (t >> 5)] = q; }
    __syncthreads();
    if (t < 8) {
        s = sm[t]; q = sm[8 + t];
#pragma unroll
        for (int o = 4; o > 0; o >>= 1) {
            s += __shfl_xor_sync(0xffu, s, o);
            q += __shfl_xor_sync(0xffu, q, o);
        }
        if (t == 0) { sm[0] = s; sm[1] = q; }
    }
    __syncthreads();
    float mu  = sm[0] * (1.0f / (float)H);
    float var = sm[1] * (1.0f / (float)H) - mu * mu;
    float inv = rsqrtf(var + 1e-5f);
    size_t base = (size_t)row * H;
#pragma unroll
    for (int e = 0; e < 3; e++) {
        int c = t + e * 256;
        float v = (e == 0) ? v0 : (e == 1) ? v1 : v2;
        float y = (v - mu) * inv * gamma[c] + beta[c];
        __nv_bfloat16 hh = __float2bfloat16(y);
        oh[base + c] = hh;
        ol[base + c] = __float2bfloat16(y - __bfloat162float(hh));
    }
}

// ---------------- 5 weights fp32 -> bf16 hi/lo in one launch -----------------
__global__ void cvt5_kernel(const float* __restrict__ s0, const float* __restrict__ s1,
                            const float* __restrict__ s2, const float* __restrict__ s3,
                            const float* __restrict__ s4,
                            __nv_bfloat16* __restrict__ h, __nv_bfloat16* __restrict__ l) {
    const int w = blockIdx.y;
    const float* s = (w == 0) ? s0 : (w == 1) ? s1 : (w == 2) ? s2 : (w == 3) ? s3 : s4;
    int i = blockIdx.x * 256 + threadIdx.x;
    if (i < H * H) {
        float v = s[i];
        __nv_bfloat16 hh = __float2bfloat16(v);
        size_t o = (size_t)w * (H * H) + i;
        h[o] = hh;
        l[o] = __float2bfloat16(v - __bfloat162float(hh));
    }
}

// ---------------- HMMA (mma.sync) GEMM ---------------------------------------
// C[M,N] = epi( A[M,K] * B[N,K]^T ), bf16 hi/lo operands, 3-pass fp32 accum.
// CTA 128x128x64, 3-stage cp.async, warp 32x64, mma m16n8k16.
// Inner loop is PASS-MAJOR: 16 independent MMAs per pass (no acc RAW chains).
// EPI 0: silu(acc+bias[n])  1: (max(acc*scale,0))^2  2: aux[m,n]*acc
// EPI 3: acc+bias[n]        4: silu(acc+bias[m])
// OUTM 0: fp32 to Cf        1: hi/lo bf16 to Ch/Cl   2: hi/lo with V^T addressing
template<int EPI, int OUTM>
__global__ void __launch_bounds__(256)
hmma_gemm(const __nv_bfloat16* __restrict__ Ah, const __nv_bfloat16* __restrict__ Al,
          const __nv_bfloat16* __restrict__ Bh, const __nv_bfloat16* __restrict__ Bl,
          const float* __restrict__ bias, const float* __restrict__ aux,
          float* __restrict__ Cf, __nv_bfloat16* __restrict__ Ch, __nv_bfloat16* __restrict__ Cl,
          int K, int ldC, long sA, long sB, long sC, float scale)
{
    extern __shared__ __align__(1024) char smem[];
    const uint32_t sb = s2u(smem);
    const int tid  = threadIdx.x;
    const int lane = tid & 31;
    const int wid  = tid >> 5;
    const int wm   = (wid & 3) * 32;    // warp M offset
    const int wn   = (wid >> 2) * 64;   // warp N offset
    const int m0 = blockIdx.y * 128;
    const int n0 = blockIdx.x * 128;
    const int bz = blockIdx.z;

    const __nv_bfloat16* gop[4];
    gop[0] = Ah + (size_t)bz * sA + (size_t)m0 * K;
    gop[1] = Al + (size_t)bz * sA + (size_t)m0 * K;
    gop[2] = Bh + (size_t)bz * sB + (size_t)n0 * K;
    gop[3] = Bl + (size_t)bz * sB + (size_t)n0 * K;

    // ldmatrix lane addressing: 128B rows, SW128 (chunk ^= row&7)
    const int rA  = lane & 15;
    const uint32_t chA  = ((lane >> 4) & 1) * 16;
    const uint32_t aOff = (uint32_t)((wm + rA) * 128) + chA;
    const uint32_t xorA = (uint32_t)(((wm + rA) & 7) << 4);
    const int rB  = (lane & 7) | (((lane >> 4) & 1) << 3);
    const uint32_t chB  = ((lane >> 3) & 1) * 16;
    const uint32_t bOff = (uint32_t)((wn + rB) * 128) + chB;
    const uint32_t xorB = (uint32_t)(((wn + rB) & 7) << 4);

    float acc[2][8][4];
#pragma unroll
    for (int a = 0; a < 2; a++)
#pragma unroll
        for (int b = 0; b < 8; b++)
#pragma unroll
            for (int c = 0; c < 4; c++) acc[a][b][c] = 0.f;

    // producer: per operand 1024 16B chunks (128 rows x 8), 4 per thread
#define LOAD_STAGE(SBASE, K0) do {                                             \
    _Pragma("unroll")                                                          \
    for (int op = 0; op < 4; op++) {                                           \
        const __nv_bfloat16* g = gop[op];                                      \
        _Pragma("unroll")                                                      \
        for (int q = 0; q < 4; q++) {                                          \
            int chk = tid + q * 256;                                           \
            int r = chk >> 3, c = chk & 7;                                     \
            uint32_t so = ((uint32_t)(r * 128 + c * 16)) ^ ((uint32_t)((r & 7) << 4)); \
            cp16(sb + (SBASE) + op * 16384u + so,                              \
                 g + (size_t)r * K + (K0) + c * 8);                            \
        }                                                                      \
    }                                                                          \
    asm volatile("cp.async.commit_group;" ::: "memory");                       \
} while (0)

    const int nch = K >> 6;
    LOAD_STAGE(0u, 0);
    LOAD_STAGE(STAGE_BYTES, 64);

    int cs = 0;   // compute stage
    for (int i = 0; i < nch; i++) {
        asm volatile("cp.async.wait_group 1;" ::: "memory");
        __syncthreads();
        if (i + 2 < nch) {
            int ls = cs + 2; if (ls >= 3) ls -= 3;
            LOAD_STAGE((uint32_t)ls * STAGE_BYTES, (i + 2) * 64);
        } else {
            asm volatile("cp.async.commit_group;" ::: "memory");
        }

        const uint32_t st = sb + (uint32_t)cs * STAGE_BYTES;
#pragma unroll
        for (int ks = 0; ks < 4; ks++) {
            // ---- load all fragments for this ks into registers ----
            uint32_t ah[2][4], al[2][4];
#pragma unroll
            for (int mt = 0; mt < 2; mt++) {
                uint32_t ad = st + aOff + (uint32_t)(mt * 2048 + ks * 32);
                ldmx4(ah[mt], ad ^ xorA);
                ldmx4(al[mt], (ad + 16384u) ^ xorA);
            }
            uint32_t bh[4][4], bl[4][4];
#pragma unroll
            for (int ng = 0; ng < 4; ng++) {
                uint32_t bd = st + 32768u + bOff + (uint32_t)(ng * 2048 + ks * 32);
                ldmx4(bh[ng], bd ^ xorB);
                ldmx4(bl[ng], (bd + 16384u) ^ xorB);
            }
            // ---- pass 1: hi*hi — 16 independent MMAs ----
#pragma unroll
            for (int ng = 0; ng < 4; ng++)
#pragma unroll
                for (int mt = 0; mt < 2; mt++)
#pragma unroll
                    for (int hf = 0; hf < 2; hf++)
                        mma16816(acc[mt][ng * 2 + hf], ah[mt],
                                 bh[ng][2 * hf], bh[ng][2 * hf + 1]);
            // ---- pass 2: hi*lo — 16 independent MMAs ----
#pragma unroll
            for (int ng = 0; ng < 4; ng++)
#pragma unroll
                for (int mt = 0; mt < 2; mt++)
#pragma unroll
                    for (int hf = 0; hf < 2; hf++)
                        mma16816(acc[mt][ng * 2 + hf], ah[mt],
                                 bl[ng][2 * hf], bl[ng][2 * hf + 1]);
            // ---- pass 3: lo*hi — 16 independent MMAs ----
#pragma unroll
            for (int ng = 0; ng < 4; ng++)
#pragma unroll
                for (int mt = 0; mt < 2; mt++)
#pragma unroll
                    for (int hf = 0; hf < 2; hf++)
                        mma16816(acc[mt][ng * 2 + hf], al[mt],
                                 bh[ng][2 * hf], bh[ng][2 * hf + 1]);
        }
        cs = (cs == 2) ? 0 : cs + 1;
    }
#undef LOAD_STAGE

    // ---------------- epilogue ----------------
    const int mB = m0 + wm + (lane >> 2);
    const int nB = n0 + wn + (lane & 3) * 2;

#pragma unroll
    for (int mt = 0; mt < 2; mt++) {
#pragma unroll
        for (int nt = 0; nt < 8; nt++) {
#pragma unroll
            for (int h = 0; h < 2; h++) {
                int m = mB + mt * 16 + h * 8;
                int n = nB + nt * 8;
                float x0 = acc[mt][nt][2 * h];
                float x1 = acc[mt][nt][2 * h + 1];

                if (EPI == 0 || EPI == 3) {
                    float2 b2 = *(const float2*)(bias + n);
                    x0 += b2.x; x1 += b2.y;
                    if (EPI == 0) {
                        x0 = x0 / (1.0f + __expf(-x0));
                        x1 = x1 / (1.0f + __expf(-x1));
                    }
                } else if (EPI == 4) {
                    float rb = bias[m];
                    x0 += rb; x1 += rb;
                    x0 = x0 / (1.0f + __expf(-x0));
                    x1 = x1 / (1.0f + __expf(-x1));
                } else if (EPI == 1) {
                    float r0 = fmaxf(x0 * scale, 0.0f);
                    float r1 = fmaxf(x1 * scale, 0.0f);
                    x0 = r0 * r0; x1 = r1 * r1;
                } else if (EPI == 2) {
                    float2 a2 = *(const float2*)(aux + (size_t)bz * sC + (size_t)m * ldC + n);
                    x0 *= a2.x; x1 *= a2.y;
                }

                if (OUTM == 0) {
                    *(float2*)(Cf + (size_t)bz * sC + (size_t)m * ldC + n) =
                        make_float2(x0, x1);
                } else {
                    size_t base;
                    if (OUTM == 1) base = (size_t)bz * sC + (size_t)m * ldC + n;
                    else {
                        int bidx = n >> 11, t = n & 2047;
                        base = (size_t)bidx * ((size_t)H * Tt) + (size_t)m * Tt + t;
                    }
                    __nv_bfloat16 h0 = __float2bfloat16(x0);
                    __nv_bfloat16 h1 = __float2bfloat16(x1);
                    __nv_bfloat162 hh; hh.x = h0; hh.y = h1;
                    __nv_bfloat162 ll;
                    ll.x = __float2bfloat16(x0 - __bfloat162float(h0));
                    ll.y = __float2bfloat16(x1 - __bfloat162float(h1));
                    *(__nv_bfloat162*)(Ch + base) = hh;
                    *(__nv_bfloat162*)(Cl + base) = ll;
                }
            }
        }
    }
}

// ---------------- host launch ------------------------------------------------
extern "C" void kernel_launch(void* const* d_in, const int* in_sizes, int n_in,
                              void* d_out, int out_size) {
    const float* hs = (const float*)d_in[0];
    const float* lg = (const float*)d_in[1];
    const float* lb = (const float*)d_in[2];
    const float* Wu = (const float*)d_in[3];
    const float* bu = (const float*)d_in[4];
    const float* Wq = (const float*)d_in[5];
    const float* bq = (const float*)d_in[6];
    const float* Wk = (const float*)d_in[7];
    const float* bk = (const float*)d_in[8];
    const float* Wv = (const float*)d_in[9];
    const float* bv = (const float*)d_in[10];
    const float* Wo = (const float*)d_in[11];
    const float* bo = (const float*)d_in[12];
    float* out = (float*)d_out;

    __nv_bfloat16 *xnh, *xnl, *Qh, *Ql, *Kh, *Kl, *Vth, *Vtl, *Sh, *Sl, *Mh, *Ml, *Wh, *Wl;
    float* U;
    cudaGetSymbolAddress((void**)&xnh, g_xnh); cudaGetSymbolAddress((void**)&xnl, g_xnl);
    cudaGetSymbolAddress((void**)&Qh,  g_Qh);  cudaGetSymbolAddress((void**)&Ql,  g_Ql);
    cudaGetSymbolAddress((void**)&Kh,  g_Kh);  cudaGetSymbolAddress((void**)&Kl,  g_Kl);
    cudaGetSymbolAddress((void**)&Vth, g_Vth); cudaGetSymbolAddress((void**)&Vtl, g_Vtl);
    cudaGetSymbolAddress((void**)&Sh,  g_Sh);  cudaGetSymbolAddress((void**)&Sl,  g_Sl);
    cudaGetSymbolAddress((void**)&Mh,  g_Mh);  cudaGetSymbolAddress((void**)&Ml,  g_Ml);
    cudaGetSymbolAddress((void**)&Wh,  g_Wh);  cudaGetSymbolAddress((void**)&Wl,  g_Wl);
    cudaGetSymbolAddress((void**)&U,   g_U);

    cudaFuncSetAttribute(hmma_gemm<0,0>, cudaFuncAttributeMaxDynamicSharedMemorySize, SMEM_BYTES);
    cudaFuncSetAttribute(hmma_gemm<0,1>, cudaFuncAttributeMaxDynamicSharedMemorySize, SMEM_BYTES);
    cudaFuncSetAttribute(hmma_gemm<4,2>, cudaFuncAttributeMaxDynamicSharedMemorySize, SMEM_BYTES);
    cudaFuncSetAttribute(hmma_gemm<1,1>, cudaFuncAttributeMaxDynamicSharedMemorySize, SMEM_BYTES);
    cudaFuncSetAttribute(hmma_gemm<2,1>, cudaFuncAttributeMaxDynamicSharedMemorySize, SMEM_BYTES);
    cudaFuncSetAttribute(hmma_gemm<3,0>, cudaFuncAttributeMaxDynamicSharedMemorySize, SMEM_BYTES);

    const float scale = 0.022097086912079608f;  // 1/sqrt(2048)
    const int NW = H * H;

    dim3 gc((NW + 255) / 256, 5, 1);
    cvt5_kernel<<<gc, 256>>>(Wu, Wq, Wk, Wv, Wo, Wh, Wl);

    ln_kernel<<<BT, 256>>>(hs, lg, lb, xnh, xnl);

    // projections: M=8192, N=768, K=768 (NT)
    dim3 gp(H / 128, BT / 128, 1);
    hmma_gemm<0,0><<<gp, 256, SMEM_BYTES>>>(xnh, xnl, Wh + 0*NW, Wl + 0*NW, bu, nullptr,
                                            U, nullptr, nullptr, H, H, 0, 0, 0, 0.f);
    hmma_gemm<0,1><<<gp, 256, SMEM_BYTES>>>(xnh, xnl, Wh + 1*NW, Wl + 1*NW, bq, nullptr,
                                            nullptr, Qh, Ql, H, H, 0, 0, 0, 0.f);
    hmma_gemm<0,1><<<gp, 256, SMEM_BYTES>>>(xnh, xnl, Wh + 2*NW, Wl + 2*NW, bk, nullptr,
                                            nullptr, Kh, Kl, H, H, 0, 0, 0, 0.f);
    // V^T = Wv @ xn^T: M=768, N=8192, K=768; silu + row bias; V^T addressing
    dim3 gv(BT / 128, H / 128, 1);
    hmma_gemm<4,2><<<gv, 256, SMEM_BYTES>>>(Wh + 3*NW, Wl + 3*NW, xnh, xnl, bv, nullptr,
                                            nullptr, Vth, Vtl, H, 0, 0, 0, 0, 0.f);
    // S = relu(QK^T * scale)^2: per batch M=N=2048, K=768
    dim3 gs(Tt / 128, Tt / 128, Bb);
    hmma_gemm<1,1><<<gs, 256, SMEM_BYTES>>>(Qh, Ql, Kh, Kl, nullptr, nullptr,
                                            nullptr, Sh, Sl, H, Tt,
                                            (long)Tt * H, (long)Tt * H, (long)Tt * Tt, scale);
    // MID = U .* (S @ V): per batch M=2048, N=768, K=2048 (B = V^T rows, K-major)
    dim3 ga(H / 128, Tt / 128, Bb);
    hmma_gemm<2,1><<<ga, 256, SMEM_BYTES>>>(Sh, Sl, Vth, Vtl, nullptr, U,
                                            nullptr, Mh, Ml, Tt, H,
                                            (long)Tt * Tt, (long)H * Tt, (long)Tt * H, 0.f);
    // out = MID @ Wo^T + bo: M=8192, N=768, K=768
    hmma_gemm<3,0><<<gp, 256, SMEM_BYTES>>>(Mh, Ml, Wh + 4*NW, Wl + 4*NW, bo, nullptr,
                                            out, nullptr, nullptr, H, H, 0, 0, 0, 0.f);
}

// round 15
// speedup vs baseline: 1.0458x; 1.0458x over previous
#include <cuda_runtime.h>
#include <cuda_bf16.h>
#include <math.h>
#include <stdint.h>

#define H 768
#define Bb 4
#define Tt 2048
#define BT (Bb*Tt)            // 8192
#define STAGE_BYTES 65536u    // 4 operand tiles * 16KB (128 rows x 128B)
#define SMEM_BYTES (3*65536)  // 3 stages

// ---------------- device scratch (no allocations allowed) --------------------
__device__ __nv_bfloat16 g_xnh[BT*H], g_xnl[BT*H];
__device__ __nv_bfloat16 g_Qh[BT*H],  g_Ql[BT*H];
__device__ __nv_bfloat16 g_Kh[BT*H],  g_Kl[BT*H];
__device__ __nv_bfloat16 g_Vth[BT*H], g_Vtl[BT*H];   // V^T: [b][d][t]
__device__ float         g_U[BT*H];
__device__ __nv_bfloat16 g_Sh[(size_t)Bb*Tt*Tt], g_Sl[(size_t)Bb*Tt*Tt];
__device__ __nv_bfloat16 g_Mh[BT*H],  g_Ml[BT*H];
__device__ __nv_bfloat16 g_Wh[5*H*H], g_Wl[5*H*H];

// ---------------- PTX helpers ------------------------------------------------
__device__ __forceinline__ uint32_t s2u(const void* p) {
    uint32_t a;
    asm("{ .reg .u64 t; cvta.to.shared.u64 t, %1; cvt.u32.u64 %0, t; }" : "=r"(a) : "l"(p));
    return a;
}
__device__ __forceinline__ void cp16(uint32_t d, const void* s) {
    asm volatile("cp.async.cg.shared.global [%0], [%1], 16;" :: "r"(d), "l"(s));
}
__device__ __forceinline__ void ldmx4(uint32_t* r, uint32_t a) {
    asm volatile("ldmatrix.sync.aligned.m8n8.x4.shared.b16 {%0,%1,%2,%3}, [%4];"
        : "=r"(r[0]), "=r"(r[1]), "=r"(r[2]), "=r"(r[3]) : "r"(a));
}
__device__ __forceinline__ void mma16816(float* c, const uint32_t* a,
                                         uint32_t b0, uint32_t b1) {
    asm volatile("mma.sync.aligned.m16n8k16.row.col.f32.bf16.bf16.f32 "
        "{%0,%1,%2,%3}, {%4,%5,%6,%7}, {%8,%9}, {%0,%1,%2,%3};"
        : "+f"(c[0]), "+f"(c[1]), "+f"(c[2]), "+f"(c[3])
        : "r"(a[0]), "r"(a[1]), "r"(a[2]), "r"(a[3]), "r"(b0), "r"(b1));
}

// ---------------- LayerNorm (fp32 math, bf16 hi/lo output) -------------------
__global__ void ln_kernel(const float* __restrict__ x, const float* __restrict__ gamma,
                          const float* __restrict__ beta,
                          __nv_bfloat16* __restrict__ oh, __nv_bfloat16* __restrict__ ol) {
    int row = blockIdx.x;
    const float* xr = x + (size_t)row * H;
    int t = threadIdx.x;
    float v0 = xr[t], v1 = xr[t + 256], v2 = xr[t + 512];
    float s = v0 + v1 + v2;
    float q = v0 * v0 + v1 * v1 + v2 * v2;
    __shared__ float sm[16];
#pragma unroll
    for (int o = 16; o > 0; o >>= 1) {
        s += __shfl_xor_sync(0xffffffffu, s, o);
        q += __shfl_xor_sync(0xffffffffu, q, o);
    }
    if ((t & 31) == 0) { sm[t >> 5] = s; sm[8 + (t >> 5)] = q; }
    __syncthreads();
    if (t < 8) {
        s = sm[t]; q = sm[8 + t];
#pragma unroll
        for (int o = 4; o > 0; o >>= 1) {
            s += __shfl_xor_sync(0xffu, s, o);
            q += __shfl_xor_sync(0xffu, q, o);
        }
        if (t == 0) { sm[0] = s; sm[1] = q; }
    }
    __syncthreads();
    float mu  = sm[0] * (1.0f / (float)H);
    float var = sm[1] * (1.0f / (float)H) - mu * mu;
    float inv = rsqrtf(var + 1e-5f);
    size_t base = (size_t)row * H;
#pragma unroll
    for (int e = 0; e < 3; e++) {
        int c = t + e * 256;
        float v = (e == 0) ? v0 : (e == 1) ? v1 : v2;
        float y = (v - mu) * inv * gamma[c] + beta[c];
        __nv_bfloat16 hh = __float2bfloat16(y);
        oh[base + c] = hh;
        ol[base + c] = __float2bfloat16(y - __bfloat162float(hh));
    }
}

// ---------------- 5 weights fp32 -> bf16 hi/lo in one launch -----------------
__global__ void cvt5_kernel(const float* __restrict__ s0, const float* __restrict__ s1,
                            const float* __restrict__ s2, const float* __restrict__ s3,
                            const float* __restrict__ s4,
                            __nv_bfloat16* __restrict__ h, __nv_bfloat16* __restrict__ l) {
    const int w = blockIdx.y;
    const float* s = (w == 0) ? s0 : (w == 1) ? s1 : (w == 2) ? s2 : (w == 3) ? s3 : s4;
    int i = blockIdx.x * 256 + threadIdx.x;
    if (i < H * H) {
        float v = s[i];
        __nv_bfloat16 hh = __float2bfloat16(v);
        size_t o = (size_t)w * (H * H) + i;
        h[o] = hh;
        l[o] = __float2bfloat16(v - __bfloat162float(hh));
    }
}

// ---------------- HMMA (mma.sync) GEMM ---------------------------------------
// C[M,N] = epi( A[M,K] * B[N,K]^T ), bf16 hi/lo operands, 3-pass fp32 accum.
// CTA 128x128x64, 512 threads, warp grid 4x4, warp tile 32x32 (4 warps/SMSP).
// 3-stage cp.async; pass-major inner loop (8 independent MMAs per pass).
// EPI 0: silu(acc+bias[n])  1: (max(acc*scale,0))^2  2: aux[m,n]*acc
// EPI 3: acc+bias[n]        4: silu(acc+bias[m])
// OUTM 0: fp32 to Cf        1: hi/lo bf16 to Ch/Cl   2: hi/lo with V^T addressing
template<int EPI, int OUTM>
__global__ void __launch_bounds__(512)
hmma_gemm(const __nv_bfloat16* __restrict__ Ah, const __nv_bfloat16* __restrict__ Al,
          const __nv_bfloat16* __restrict__ Bh, const __nv_bfloat16* __restrict__ Bl,
          const float* __restrict__ bias, const float* __restrict__ aux,
          float* __restrict__ Cf, __nv_bfloat16* __restrict__ Ch, __nv_bfloat16* __restrict__ Cl,
          int K, int ldC, long sA, long sB, long sC, float scale)
{
    extern __shared__ __align__(1024) char smem[];
    const uint32_t sb = s2u(smem);
    const int tid  = threadIdx.x;
    const int lane = tid & 31;
    const int wid  = tid >> 5;
    const int wm   = (wid & 3) * 32;    // warp M offset (4 warps over M)
    const int wn   = (wid >> 2) * 32;   // warp N offset (4 warps over N)
    const int m0 = blockIdx.y * 128;
    const int n0 = blockIdx.x * 128;
    const int bz = blockIdx.z;

    const __nv_bfloat16* gop[4];
    gop[0] = Ah + (size_t)bz * sA + (size_t)m0 * K;
    gop[1] = Al + (size_t)bz * sA + (size_t)m0 * K;
    gop[2] = Bh + (size_t)bz * sB + (size_t)n0 * K;
    gop[3] = Bl + (size_t)bz * sB + (size_t)n0 * K;

    // ldmatrix lane addressing: 128B rows, SW128 (chunk ^= row&7)
    const int rA  = lane & 15;
    const uint32_t chA  = ((lane >> 4) & 1) * 16;
    const uint32_t aOff = (uint32_t)((wm + rA) * 128) + chA;
    const uint32_t xorA = (uint32_t)(((wm + rA) & 7) << 4);
    const int rB  = (lane & 7) | (((lane >> 4) & 1) << 3);
    const uint32_t chB  = ((lane >> 3) & 1) * 16;
    const uint32_t bOff = (uint32_t)((wn + rB) * 128) + chB;
    const uint32_t xorB = (uint32_t)(((wn + rB) & 7) << 4);

    float acc[2][4][4];
#pragma unroll
    for (int a = 0; a < 2; a++)
#pragma unroll
        for (int b = 0; b < 4; b++)
#pragma unroll
            for (int c = 0; c < 4; c++) acc[a][b][c] = 0.f;

    // producer: per operand 1024 16B chunks (128 rows x 8), 2 per thread
#define LOAD_STAGE(SBASE, K0) do {                                             \
    _Pragma("unroll")                                                          \
    for (int op = 0; op < 4; op++) {                                           \
        const __nv_bfloat16* g = gop[op];                                      \
        _Pragma("unroll")                                                      \
        for (int q = 0; q < 2; q++) {                                          \
            int chk = tid + q * 512;                                           \
            int r = chk >> 3, c = chk & 7;                                     \
            uint32_t so = ((uint32_t)(r * 128 + c * 16)) ^ ((uint32_t)((r & 7) << 4)); \
            cp16(sb + (SBASE) + op * 16384u + so,                              \
                 g + (size_t)r * K + (K0) + c * 8);                            \
        }                                                                      \
    }                                                                          \
    asm volatile("cp.async.commit_group;" ::: "memory");                       \
} while (0)

    const int nch = K >> 6;
    LOAD_STAGE(0u, 0);
    LOAD_STAGE(STAGE_BYTES, 64);

    int cs = 0;   // compute stage
    for (int i = 0; i < nch; i++) {
        asm volatile("cp.async.wait_group 1;" ::: "memory");
        __syncthreads();
        if (i + 2 < nch) {
            int ls = cs + 2; if (ls >= 3) ls -= 3;
            LOAD_STAGE((uint32_t)ls * STAGE_BYTES, (i + 2) * 64);
        } else {
            asm volatile("cp.async.commit_group;" ::: "memory");
        }

        const uint32_t st = sb + (uint32_t)cs * STAGE_BYTES;
#pragma unroll
        for (int ks = 0; ks < 4; ks++) {
            // ---- load fragments for this ks ----
            uint32_t ah[2][4], al[2][4];
#pragma unroll
            for (int mt = 0; mt < 2; mt++) {
                uint32_t ad = st + aOff + (uint32_t)(mt * 2048 + ks * 32);
                ldmx4(ah[mt], ad ^ xorA);
                ldmx4(al[mt], (ad + 16384u) ^ xorA);
            }
            uint32_t bh[2][4], bl[2][4];
#pragma unroll
            for (int ng = 0; ng < 2; ng++) {
                uint32_t bd = st + 32768u + bOff + (uint32_t)(ng * 2048 + ks * 32);
                ldmx4(bh[ng], bd ^ xorB);
                ldmx4(bl[ng], (bd + 16384u) ^ xorB);
            }
            // ---- pass 1: hi*hi ----
#pragma unroll
            for (int ng = 0; ng < 2; ng++)
#pragma unroll
                for (int mt = 0; mt < 2; mt++)
#pragma unroll
                    for (int hf = 0; hf < 2; hf++)
                        mma16816(acc[mt][ng * 2 + hf], ah[mt],
                                 bh[ng][2 * hf], bh[ng][2 * hf + 1]);
            // ---- pass 2: hi*lo ----
#pragma unroll
            for (int ng = 0; ng < 2; ng++)
#pragma unroll
                for (int mt = 0; mt < 2; mt++)
#pragma unroll
                    for (int hf = 0; hf < 2; hf++)
                        mma16816(acc[mt][ng * 2 + hf], ah[mt],
                                 bl[ng][2 * hf], bl[ng][2 * hf + 1]);
            // ---- pass 3: lo*hi ----
#pragma unroll
            for (int ng = 0; ng < 2; ng++)
#pragma unroll
                for (int mt = 0; mt < 2; mt++)
#pragma unroll
                    for (int hf = 0; hf < 2; hf++)
                        mma16816(acc[mt][ng * 2 + hf], al[mt],
                                 bh[ng][2 * hf], bh[ng][2 * hf + 1]);
        }
        cs = (cs == 2) ? 0 : cs + 1;
    }
#undef LOAD_STAGE

    // ---------------- epilogue ----------------
    const int mB = m0 + wm + (lane >> 2);
    const int nB = n0 + wn + (lane & 3) * 2;

#pragma unroll
    for (int mt = 0; mt < 2; mt++) {
#pragma unroll
        for (int nt = 0; nt < 4; nt++) {
#pragma unroll
            for (int h = 0; h < 2; h++) {
                int m = mB + mt * 16 + h * 8;
                int n = nB + nt * 8;
                float x0 = acc[mt][nt][2 * h];
                float x1 = acc[mt][nt][2 * h + 1];

                if (EPI == 0 || EPI == 3) {
                    float2 b2 = *(const float2*)(bias + n);
                    x0 += b2.x; x1 += b2.y;
                    if (EPI == 0) {
                        x0 = x0 / (1.0f + __expf(-x0));
                        x1 = x1 / (1.0f + __expf(-x1));
                    }
                } else if (EPI == 4) {
                    float rb = bias[m];
                    x0 += rb; x1 += rb;
                    x0 = x0 / (1.0f + __expf(-x0));
                    x1 = x1 / (1.0f + __expf(-x1));
                } else if (EPI == 1) {
                    float r0 = fmaxf(x0 * scale, 0.0f);
                    float r1 = fmaxf(x1 * scale, 0.0f);
                    x0 = r0 * r0; x1 = r1 * r1;
                } else if (EPI == 2) {
                    float2 a2 = *(const float2*)(aux + (size_t)bz * sC + (size_t)m * ldC + n);
                    x0 *= a2.x; x1 *= a2.y;
                }

                if (OUTM == 0) {
                    *(float2*)(Cf + (size_t)bz * sC + (size_t)m * ldC + n) =
                        make_float2(x0, x1);
                } else {
                    size_t base;
                    if (OUTM == 1) base = (size_t)bz * sC + (size_t)m * ldC + n;
                    else {
                        int bidx = n >> 11, t = n & 2047;
                        base = (size_t)bidx * ((size_t)H * Tt) + (size_t)m * Tt + t;
                    }
                    __nv_bfloat16 h0 = __float2bfloat16(x0);
                    __nv_bfloat16 h1 = __float2bfloat16(x1);
                    __nv_bfloat162 hh; hh.x = h0; hh.y = h1;
                    __nv_bfloat162 ll;
                    ll.x = __float2bfloat16(x0 - __bfloat162float(h0));
                    ll.y = __float2bfloat16(x1 - __bfloat162float(h1));
                    *(__nv_bfloat162*)(Ch + base) = hh;
                    *(__nv_bfloat162*)(Cl + base) = ll;
                }
            }
        }
    }
}

// ---------------- host launch ------------------------------------------------
extern "C" void kernel_launch(void* const* d_in, const int* in_sizes, int n_in,
                              void* d_out, int out_size) {
    const float* hs = (const float*)d_in[0];
    const float* lg = (const float*)d_in[1];
    const float* lb = (const float*)d_in[2];
    const float* Wu = (const float*)d_in[3];
    const float* bu = (const float*)d_in[4];
    const float* Wq = (const float*)d_in[5];
    const float* bq = (const float*)d_in[6];
    const float* Wk = (const float*)d_in[7];
    const float* bk = (const float*)d_in[8];
    const float* Wv = (const float*)d_in[9];
    const float* bv = (const float*)d_in[10];
    const float* Wo = (const float*)d_in[11];
    const float* bo = (const float*)d_in[12];
    float* out = (float*)d_out;

    __nv_bfloat16 *xnh, *xnl, *Qh, *Ql, *Kh, *Kl, *Vth, *Vtl, *Sh, *Sl, *Mh, *Ml, *Wh, *Wl;
    float* U;
    cudaGetSymbolAddress((void**)&xnh, g_xnh); cudaGetSymbolAddress((void**)&xnl, g_xnl);
    cudaGetSymbolAddress((void**)&Qh,  g_Qh);  cudaGetSymbolAddress((void**)&Ql,  g_Ql);
    cudaGetSymbolAddress((void**)&Kh,  g_Kh);  cudaGetSymbolAddress((void**)&Kl,  g_Kl);
    cudaGetSymbolAddress((void**)&Vth, g_Vth); cudaGetSymbolAddress((void**)&Vtl, g_Vtl);
    cudaGetSymbolAddress((void**)&Sh,  g_Sh);  cudaGetSymbolAddress((void**)&Sl,  g_Sl);
    cudaGetSymbolAddress((void**)&Mh,  g_Mh);  cudaGetSymbolAddress((void**)&Ml,  g_Ml);
    cudaGetSymbolAddress((void**)&Wh,  g_Wh);  cudaGetSymbolAddress((void**)&Wl,  g_Wl);
    cudaGetSymbolAddress((void**)&U,   g_U);

    cudaFuncSetAttribute(hmma_gemm<0,0>, cudaFuncAttributeMaxDynamicSharedMemorySize, SMEM_BYTES);
    cudaFuncSetAttribute(hmma_gemm<0,1>, cudaFuncAttributeMaxDynamicSharedMemorySize, SMEM_BYTES);
    cudaFuncSetAttribute(hmma_gemm<4,2>, cudaFuncAttributeMaxDynamicSharedMemorySize, SMEM_BYTES);
    cudaFuncSetAttribute(hmma_gemm<1,1>, cudaFuncAttributeMaxDynamicSharedMemorySize, SMEM_BYTES);
    cudaFuncSetAttribute(hmma_gemm<2,1>, cudaFuncAttributeMaxDynamicSharedMemorySize, SMEM_BYTES);
    cudaFuncSetAttribute(hmma_gemm<3,0>, cudaFuncAttributeMaxDynamicSharedMemorySize, SMEM_BYTES);

    const float scale = 0.022097086912079608f;  // 1/sqrt(2048)
    const int NW = H * H;

    dim3 gc((NW + 255) / 256, 5, 1);
    cvt5_kernel<<<gc, 256>>>(Wu, Wq, Wk, Wv, Wo, Wh, Wl);

    ln_kernel<<<BT, 256>>>(hs, lg, lb, xnh, xnl);

    // projections: M=8192, N=768, K=768 (NT)
    dim3 gp(H / 128, BT / 128, 1);
    hmma_gemm<0,0><<<gp, 512, SMEM_BYTES>>>(xnh, xnl, Wh + 0*NW, Wl + 0*NW, bu, nullptr,
                                            U, nullptr, nullptr, H, H, 0, 0, 0, 0.f);
    hmma_gemm<0,1><<<gp, 512, SMEM_BYTES>>>(xnh, xnl, Wh + 1*NW, Wl + 1*NW, bq, nullptr,
                                            nullptr, Qh, Ql, H, H, 0, 0, 0, 0.f);
    hmma_gemm<0,1><<<gp, 512, SMEM_BYTES>>>(xnh, xnl, Wh + 2*NW, Wl + 2*NW, bk, nullptr,
                                            nullptr, Kh, Kl, H, H, 0, 0, 0, 0.f);
    // V^T = Wv @ xn^T: M=768, N=8192, K=768; silu + row bias; V^T addressing
    dim3 gv(BT / 128, H / 128, 1);
    hmma_gemm<4,2><<<gv, 512, SMEM_BYTES>>>(Wh + 3*NW, Wl + 3*NW, xnh, xnl, bv, nullptr,
                                            nullptr, Vth, Vtl, H, 0, 0, 0, 0, 0.f);
    // S = relu(QK^T * scale)^2: per batch M=N=2048, K=768
    dim3 gs(Tt / 128, Tt / 128, Bb);
    hmma_gemm<1,1><<<gs, 512, SMEM_BYTES>>>(Qh, Ql, Kh, Kl, nullptr, nullptr,
                                            nullptr, Sh, Sl, H, Tt,
                                            (long)Tt * H, (long)Tt * H, (long)Tt * Tt, scale);
    // MID = U .* (S @ V): per batch M=2048, N=768, K=2048 (B = V^T rows, K-major)
    dim3 ga(H / 128, Tt / 128, Bb);
    hmma_gemm<2,1><<<ga, 512, SMEM_BYTES>>>(Sh, Sl, Vth, Vtl, nullptr, U,
                                            nullptr, Mh, Ml, Tt, H,
                                            (long)Tt * Tt, (long)H * Tt, (long)Tt * H, 0.f);
    // out = MID @ Wo^T + bo: M=8192, N=768, K=768
    hmma_gemm<3,0><<<gp, 512, SMEM_BYTES>>>(Mh, Ml, Wh + 4*NW, Wl + 4*NW, bo, nullptr,
                                            out, nullptr, nullptr, H, H, 0, 0, 0, 0.f);
}

// round 17
// speedup vs baseline: 1.1114x; 1.0627x over previous
#include <cuda_runtime.h>
#include <cuda_bf16.h>
#include <math.h>
#include <stdint.h>

#define H 768
#define Bb 4
#define Tt 2048
#define BT (Bb*Tt)            // 8192
#define STAGE_BYTES 32768u    // 4 operand tiles * 8KB (128 rows x 64B, BK=32)
#define SMEM_BYTES (3*32768)  // 3 stages = 96KB -> 2 CTAs/SM

// ---------------- device scratch (no allocations allowed) --------------------
__device__ __nv_bfloat16 g_xnh[BT*H], g_xnl[BT*H];
__device__ __nv_bfloat16 g_Qh[BT*H],  g_Ql[BT*H];
__device__ __nv_bfloat16 g_Kh[BT*H],  g_Kl[BT*H];
__device__ __nv_bfloat16 g_Vth[BT*H], g_Vtl[BT*H];   // V^T: [b][d][t]
__device__ float         g_U[BT*H];
__device__ __nv_bfloat16 g_Sh[(size_t)Bb*Tt*Tt], g_Sl[(size_t)Bb*Tt*Tt];
__device__ __nv_bfloat16 g_Mh[BT*H],  g_Ml[BT*H];
__device__ __nv_bfloat16 g_Wh[5*H*H], g_Wl[5*H*H];
__device__ float         g_b3[3*H];   // packed [bu; bq; bk]

// ---------------- PTX helpers ------------------------------------------------
__device__ __forceinline__ uint32_t s2u(const void* p) {
    uint32_t a;
    asm("{ .reg .u64 t; cvta.to.shared.u64 t, %1; cvt.u32.u64 %0, t; }" : "=r"(a) : "l"(p));
    return a;
}
__device__ __forceinline__ void cp16(uint32_t d, const void* s) {
    asm volatile("cp.async.cg.shared.global [%0], [%1], 16;" :: "r"(d), "l"(s));
}
__device__ __forceinline__ void ldmx4(uint32_t* r, uint32_t a) {
    asm volatile("ldmatrix.sync.aligned.m8n8.x4.shared.b16 {%0,%1,%2,%3}, [%4];"
        : "=r"(r[0]), "=r"(r[1]), "=r"(r[2]), "=r"(r[3]) : "r"(a));
}
__device__ __forceinline__ void mma16816(float* c, const uint32_t* a,
                                         uint32_t b0, uint32_t b1) {
    asm volatile("mma.sync.aligned.m16n8k16.row.col.f32.bf16.bf16.f32 "
        "{%0,%1,%2,%3}, {%4,%5,%6,%7}, {%8,%9}, {%0,%1,%2,%3};"
        : "+f"(c[0]), "+f"(c[1]), "+f"(c[2]), "+f"(c[3])
        : "r"(a[0]), "r"(a[1]), "r"(a[2]), "r"(a[3]), "r"(b0), "r"(b1));
}

// ---------------- LayerNorm (fp32 math, bf16 hi/lo output) -------------------
__global__ void ln_kernel(const float* __restrict__ x, const float* __restrict__ gamma,
                          const float* __restrict__ beta,
                          __nv_bfloat16* __restrict__ oh, __nv_bfloat16* __restrict__ ol) {
    int row = blockIdx.x;
    const float* xr = x + (size_t)row * H;
    int t = threadIdx.x;
    float v0 = xr[t], v1 = xr[t + 256], v2 = xr[t + 512];
    float s = v0 + v1 + v2;
    float q = v0 * v0 + v1 * v1 + v2 * v2;
    __shared__ float sm[16];
#pragma unroll
    for (int o = 16; o > 0; o >>= 1) {
        s += __shfl_xor_sync(0xffffffffu, s, o);
        q += __shfl_xor_sync(0xffffffffu, q, o);
    }
    if ((t & 31) == 0) { sm[t >> 5] = s; sm[8 + (t >> 5)] = q; }
    __syncthreads();
    if (t < 8) {
        s = sm[t]; q = sm[8 + t];
#pragma unroll
        for (int o = 4; o > 0; o >>= 1) {
            s += __shfl_xor_sync(0xffu, s, o);
            q += __shfl_xor_sync(0xffu, q, o);
        }
        if (t == 0) { sm[0] = s; sm[1] = q; }
    }
    __syncthreads();
    float mu  = sm[0] * (1.0f / (float)H);
    float var = sm[1] * (1.0f / (float)H) - mu * mu;
    float inv = rsqrtf(var + 1e-5f);
    size_t base = (size_t)row * H;
#pragma unroll
    for (int e = 0; e < 3; e++) {
        int c = t + e * 256;
        float v = (e == 0) ? v0 : (e == 1) ? v1 : v2;
        float y = (v - mu) * inv * gamma[c] + beta[c];
        __nv_bfloat16 hh = __float2bfloat16(y);
        oh[base + c] = hh;
        ol[base + c] = __float2bfloat16(y - __bfloat162float(hh));
    }
}

// ---------------- weights fp32 -> bf16 hi/lo + bias pack ---------------------
__global__ void cvt5_kernel(const float* __restrict__ s0, const float* __restrict__ s1,
                            const float* __restrict__ s2, const float* __restrict__ s3,
                            const float* __restrict__ s4,
                            const float* __restrict__ bu, const float* __restrict__ bq,
                            const float* __restrict__ bk,
                            __nv_bfloat16* __restrict__ h, __nv_bfloat16* __restrict__ l,
                            float* __restrict__ b3) {
    const int w = blockIdx.y;
    const float* s = (w == 0) ? s0 : (w == 1) ? s1 : (w == 2) ? s2 : (w == 3) ? s3 : s4;
    int i = blockIdx.x * 256 + threadIdx.x;
    if (i < H * H) {
        float v = s[i];
        __nv_bfloat16 hh = __float2bfloat16(v);
        size_t o = (size_t)w * (H * H) + i;
        h[o] = hh;
        l[o] = __float2bfloat16(v - __bfloat162float(hh));
    }
    if (w < 3 && blockIdx.x == 0 && threadIdx.x < 256) {
        const float* bp = (w == 0) ? bu : (w == 1) ? bq : bk;
        for (int c = threadIdx.x; c < H; c += 256) b3[w * H + c] = bp[c];
    }
}

// ---------------- HMMA (mma.sync) GEMM ---------------------------------------
// C[M,N] = epi( A[M,K] * B[N,K]^T ), bf16 hi/lo operands, 3-pass fp32 accum.
// CTA 128x128xBK32, 128 threads, warp grid 2x2, warp tile 64x64, 3-stage,
// 2 CTAs/SM. Pass-major inner loop (32 independent MMAs per pass).
// EPI 0: silu(acc+bias[n])  1: (max(acc*scale,0))^2  2: aux[m,n]*acc
// EPI 3: acc+bias[n]        4: silu(acc+bias[m])
// OUTM 0: fp32->Cf  1: hi/lo->Ch/Cl  2: hi/lo V^T addressing
// OUTM 3: merged UQK: sec=n0/768: 0->fp32 Cf, 1->Ch/Cl, 2->Ch2/Cl2 (ldC=768)
template<int EPI, int OUTM>
__global__ void __launch_bounds__(128, 2)
hmma_gemm(const __nv_bfloat16* __restrict__ Ah, const __nv_bfloat16* __restrict__ Al,
          const __nv_bfloat16* __restrict__ Bh, const __nv_bfloat16* __restrict__ Bl,
          const float* __restrict__ bias, const float* __restrict__ aux,
          float* __restrict__ Cf, __nv_bfloat16* __restrict__ Ch, __nv_bfloat16* __restrict__ Cl,
          __nv_bfloat16* __restrict__ Ch2, __nv_bfloat16* __restrict__ Cl2,
          int K, int ldC, long sA, long sB, long sC, float scale)
{
    extern __shared__ __align__(1024) char smem[];
    const uint32_t sb = s2u(smem);
    const int tid  = threadIdx.x;
    const int lane = tid & 31;
    const int wid  = tid >> 5;
    const int wm   = (wid & 1) * 64;    // warp M offset (2 over M)
    const int wn   = (wid >> 1) * 64;   // warp N offset (2 over N)
    const int m0 = blockIdx.y * 128;
    const int n0 = blockIdx.x * 128;
    const int bz = blockIdx.z;

    const __nv_bfloat16* gop[4];
    gop[0] = Ah + (size_t)bz * sA + (size_t)m0 * K;
    gop[1] = Al + (size_t)bz * sA + (size_t)m0 * K;
    gop[2] = Bh + (size_t)bz * sB + (size_t)n0 * K;
    gop[3] = Bl + (size_t)bz * sB + (size_t)n0 * K;

    // ldmatrix lane addressing: 64B rows, swizzle chunk ^= ((row>>1)&3)<<4
    const int rA  = lane & 15;
    const uint32_t chA  = ((lane >> 4) & 1) * 16;
    const uint32_t aOff = (uint32_t)((wm + rA) * 64) + chA;
    const uint32_t xorA = (uint32_t)(((rA >> 1) & 3) << 4);
    const int rB  = (lane & 7) | (((lane >> 4) & 1) << 3);
    const uint32_t chB  = ((lane >> 3) & 1) * 16;
    const uint32_t bOff = (uint32_t)((wn + rB) * 64) + chB;
    const uint32_t xorB = (uint32_t)(((rB >> 1) & 3) << 4);

    float acc[4][8][4];
#pragma unroll
    for (int a = 0; a < 4; a++)
#pragma unroll
        for (int b = 0; b < 8; b++)
#pragma unroll
            for (int c = 0; c < 4; c++) acc[a][b][c] = 0.f;

    // producer: per operand 512 16B chunks (128 rows x 4), 4 per thread
#define LOAD_STAGE(SBASE, K0) do {                                             \
    _Pragma("unroll")                                                          \
    for (int op = 0; op < 4; op++) {                                           \
        const __nv_bfloat16* g = gop[op];                                      \
        _Pragma("unroll")                                                      \
        for (int q = 0; q < 4; q++) {                                          \
            int chk = tid + q * 128;                                           \
            int r = chk >> 2, c = chk & 3;                                     \
            uint32_t so = ((uint32_t)(r * 64 + c * 16)) ^ ((uint32_t)(((r >> 1) & 3) << 4)); \
            cp16(sb + (SBASE) + op * 8192u + so,                               \
                 g + (size_t)r * K + (K0) + c * 8);                            \
        }                                                                      \
    }                                                                          \
    asm volatile("cp.async.commit_group;" ::: "memory");                       \
} while (0)

    const int nch = K >> 5;
    LOAD_STAGE(0u, 0);
    LOAD_STAGE(STAGE_BYTES, 32);

    int cs = 0;   // compute stage
    for (int i = 0; i < nch; i++) {
        asm volatile("cp.async.wait_group 1;" ::: "memory");
        __syncthreads();
        if (i + 2 < nch) {
            int ls = cs + 2; if (ls >= 3) ls -= 3;
            LOAD_STAGE((uint32_t)ls * STAGE_BYTES, (i + 2) * 32);
        } else {
            asm volatile("cp.async.commit_group;" ::: "memory");
        }

        const uint32_t st = sb + (uint32_t)cs * STAGE_BYTES;
#pragma unroll
        for (int ks = 0; ks < 2; ks++) {
            // ---- fragments for this k16 step ----
            uint32_t ah[4][4], al[4][4];
#pragma unroll
            for (int mt = 0; mt < 4; mt++) {
                uint32_t ad = st + aOff + (uint32_t)(mt * 1024 + ks * 32);
                ldmx4(ah[mt], ad ^ xorA);
                ldmx4(al[mt], (ad + 8192u) ^ xorA);
            }
            uint32_t bh[4][4], bl[4][4];
#pragma unroll
            for (int ng = 0; ng < 4; ng++) {
                uint32_t bd = st + 16384u + bOff + (uint32_t)(ng * 1024 + ks * 32);
                ldmx4(bh[ng], bd ^ xorB);
                ldmx4(bl[ng], (bd + 8192u) ^ xorB);
            }
            // ---- pass 1: hi*hi — 32 independent MMAs ----
#pragma unroll
            for (int ng = 0; ng < 4; ng++)
#pragma unroll
                for (int mt = 0; mt < 4; mt++)
#pragma unroll
                    for (int hf = 0; hf < 2; hf++)
                        mma16816(acc[mt][ng * 2 + hf], ah[mt],
                                 bh[ng][2 * hf], bh[ng][2 * hf + 1]);
            // ---- pass 2: hi*lo ----
#pragma unroll
            for (int ng = 0; ng < 4; ng++)
#pragma unroll
                for (int mt = 0; mt < 4; mt++)
#pragma unroll
                    for (int hf = 0; hf < 2; hf++)
                        mma16816(acc[mt][ng * 2 + hf], ah[mt],
                                 bl[ng][2 * hf], bl[ng][2 * hf + 1]);
            // ---- pass 3: lo*hi ----
#pragma unroll
            for (int ng = 0; ng < 4; ng++)
#pragma unroll
                for (int mt = 0; mt < 4; mt++)
#pragma unroll
                    for (int hf = 0; hf < 2; hf++)
                        mma16816(acc[mt][ng * 2 + hf], al[mt],
                                 bh[ng][2 * hf], bh[ng][2 * hf + 1]);
        }
        cs = (cs == 2) ? 0 : cs + 1;
    }
#undef LOAD_STAGE

    // ---------------- epilogue ----------------
    const int mB = m0 + wm + (lane >> 2);
    const int nB = n0 + wn + (lane & 3) * 2;
    // merged-projection section select (uniform per CTA; 768 % 128 == 0)
    int sec = 0, nsub = 0;
    if (OUTM == 3) { sec = n0 / H; nsub = -sec * H; }

#pragma unroll
    for (int mt = 0; mt < 4; mt++) {
#pragma unroll
        for (int nt = 0; nt < 8; nt++) {
#pragma unroll
            for (int h = 0; h < 2; h++) {
                int m = mB + mt * 16 + h * 8;
                int n = nB + nt * 8;
                float x0 = acc[mt][nt][2 * h];
                float x1 = acc[mt][nt][2 * h + 1];

                if (EPI == 0 || EPI == 3) {
                    float2 b2 = *(const float2*)(bias + n);
                    x0 += b2.x; x1 += b2.y;
                    if (EPI == 0) {
                        x0 = x0 / (1.0f + __expf(-x0));
                        x1 = x1 / (1.0f + __expf(-x1));
                    }
                } else if (EPI == 4) {
                    float rb = bias[m];
                    x0 += rb; x1 += rb;
                    x0 = x0 / (1.0f + __expf(-x0));
                    x1 = x1 / (1.0f + __expf(-x1));
                } else if (EPI == 1) {
                    float r0 = fmaxf(x0 * scale, 0.0f);
                    float r1 = fmaxf(x1 * scale, 0.0f);
                    x0 = r0 * r0; x1 = r1 * r1;
                } else if (EPI == 2) {
                    float2 a2 = *(const float2*)(aux + (size_t)bz * sC + (size_t)m * ldC + n);
                    x0 *= a2.x; x1 *= a2.y;
                }

                if (OUTM == 0) {
                    *(float2*)(Cf + (size_t)bz * sC + (size_t)m * ldC + n) =
                        make_float2(x0, x1);
                } else if (OUTM == 3 && sec == 0) {
                    *(float2*)(Cf + (size_t)m * H + n) = make_float2(x0, x1);
                } else {
                    size_t base;
                    __nv_bfloat16 *dh, *dl;
                    if (OUTM == 1) {
                        base = (size_t)bz * sC + (size_t)m * ldC + n;
                        dh = Ch; dl = Cl;
                    } else if (OUTM == 2) {
                        int bidx = n >> 11, t = n & 2047;
                        base = (size_t)bidx * ((size_t)H * Tt) + (size_t)m * Tt + t;
                        dh = Ch; dl = Cl;
                    } else {  // OUTM == 3, sec 1/2
                        base = (size_t)m * H + (n + nsub);
                        dh = (sec == 1) ? Ch : Ch2;
                        dl = (sec == 1) ? Cl : Cl2;
                    }
                    __nv_bfloat16 h0 = __float2bfloat16(x0);
                    __nv_bfloat16 h1 = __float2bfloat16(x1);
                    __nv_bfloat162 hh; hh.x = h0; hh.y = h1;
                    __nv_bfloat162 ll;
                    ll.x = __float2bfloat16(x0 - __bfloat162float(h0));
                    ll.y = __float2bfloat16(x1 - __bfloat162float(h1));
                    *(__nv_bfloat162*)(dh + base) = hh;
                    *(__nv_bfloat162*)(dl + base) = ll;
                }
            }
        }
    }
}

// ---------------- host launch ------------------------------------------------
extern "C" void kernel_launch(void* const* d_in, const int* in_sizes, int n_in,
                              void* d_out, int out_size) {
    const float* hs = (const float*)d_in[0];
    const float* lg = (const float*)d_in[1];
    const float* lb = (const float*)d_in[2];
    const float* Wu = (const float*)d_in[3];
    const float* bu = (const float*)d_in[4];
    const float* Wq = (const float*)d_in[5];
    const float* bq = (const float*)d_in[6];
    const float* Wk = (const float*)d_in[7];
    const float* bk = (const float*)d_in[8];
    const float* Wv = (const float*)d_in[9];
    const float* bv = (const float*)d_in[10];
    const float* Wo = (const float*)d_in[11];
    const float* bo = (const float*)d_in[12];
    float* out = (float*)d_out;

    __nv_bfloat16 *xnh, *xnl, *Qh, *Ql, *Kh, *Kl, *Vth, *Vtl, *Sh, *Sl, *Mh, *Ml, *Wh, *Wl;
    float *U, *b3;
    cudaGetSymbolAddress((void**)&xnh, g_xnh); cudaGetSymbolAddress((void**)&xnl, g_xnl);
    cudaGetSymbolAddress((void**)&Qh,  g_Qh);  cudaGetSymbolAddress((void**)&Ql,  g_Ql);
    cudaGetSymbolAddress((void**)&Kh,  g_Kh);  cudaGetSymbolAddress((void**)&Kl,  g_Kl);
    cudaGetSymbolAddress((void**)&Vth, g_Vth); cudaGetSymbolAddress((void**)&Vtl, g_Vtl);
    cudaGetSymbolAddress((void**)&Sh,  g_Sh);  cudaGetSymbolAddress((void**)&Sl,  g_Sl);
    cudaGetSymbolAddress((void**)&Mh,  g_Mh);  cudaGetSymbolAddress((void**)&Ml,  g_Ml);
    cudaGetSymbolAddress((void**)&Wh,  g_Wh);  cudaGetSymbolAddress((void**)&Wl,  g_Wl);
    cudaGetSymbolAddress((void**)&U,   g_U);   cudaGetSymbolAddress((void**)&b3,  g_b3);

    cudaFuncSetAttribute(hmma_gemm<0,3>, cudaFuncAttributeMaxDynamicSharedMemorySize, SMEM_BYTES);
    cudaFuncSetAttribute(hmma_gemm<4,2>, cudaFuncAttributeMaxDynamicSharedMemorySize, SMEM_BYTES);
    cudaFuncSetAttribute(hmma_gemm<1,1>, cudaFuncAttributeMaxDynamicSharedMemorySize, SMEM_BYTES);
    cudaFuncSetAttribute(hmma_gemm<2,1>, cudaFuncAttributeMaxDynamicSharedMemorySize, SMEM_BYTES);
    cudaFuncSetAttribute(hmma_gemm<3,0>, cudaFuncAttributeMaxDynamicSharedMemorySize, SMEM_BYTES);

    const float scale = 0.022097086912079608f;  // 1/sqrt(2048)
    const int NW = H * H;

    dim3 gc((NW + 255) / 256, 5, 1);
    cvt5_kernel<<<gc, 256>>>(Wu, Wq, Wk, Wv, Wo, bu, bq, bk, Wh, Wl, b3);

    ln_kernel<<<BT, 256>>>(hs, lg, lb, xnh, xnl);

    // merged U,Q,K projections: M=8192, N=2304, K=768 (NT)
    dim3 gm(3 * H / 128, BT / 128, 1);
    hmma_gemm<0,3><<<gm, 128, SMEM_BYTES>>>(xnh, xnl, Wh, Wl, b3, nullptr,
                                            U, Qh, Ql, Kh, Kl, H, H, 0, 0, 0, 0.f);
    // V^T = Wv @ xn^T: M=768, N=8192, K=768; silu + row bias; V^T addressing
    dim3 gv(BT / 128, H / 128, 1);
    hmma_gemm<4,2><<<gv, 128, SMEM_BYTES>>>(Wh + 3*NW, Wl + 3*NW, xnh, xnl, bv, nullptr,
                                            nullptr, Vth, Vtl, nullptr, nullptr,
                                            H, 0, 0, 0, 0, 0.f);
    // S = relu(QK^T * scale)^2: per batch M=N=2048, K=768
    dim3 gs(Tt / 128, Tt / 128, Bb);
    hmma_gemm<1,1><<<gs, 128, SMEM_BYTES>>>(Qh, Ql, Kh, Kl, nullptr, nullptr,
                                            nullptr, Sh, Sl, nullptr, nullptr, H, Tt,
                                            (long)Tt * H, (long)Tt * H, (long)Tt * Tt, scale);
    // MID = U .* (S @ V): per batch M=2048, N=768, K=2048 (B = V^T rows, K-major)
    dim3 ga(H / 128, Tt / 128, Bb);
    hmma_gemm<2,1><<<ga, 128, SMEM_BYTES>>>(Sh, Sl, Vth, Vtl, nullptr, U,
                                            nullptr, Mh, Ml, nullptr, nullptr, Tt, H,
                                            (long)Tt * Tt, (long)H * Tt, (long)Tt * H, 0.f);
    // out = MID @ Wo^T + bo: M=8192, N=768, K=768
    dim3 gp(H / 128, BT / 128, 1);
    hmma_gemm<3,0><<<gp, 128, SMEM_BYTES>>>(Mh, Ml, Wh + 4*NW, Wl + 4*NW, bo, nullptr,
                                            out, nullptr, nullptr, nullptr, nullptr,
                                            H, H, 0, 0, 0, 0.f);
}